// round 5
// baseline (speedup 1.0000x reference)
#include <cuda_runtime.h>
#include <cuda_bf16.h>
#include <cstdint>

#define B_DIM 128
#define E_DIM 512
#define H_DIM 1024
#define S_DIM 514
#define M_ROWS 65536
#define NEG_V (-1000000.0f)

// ---------------- device scratch ----------------
__device__ int8_t g_keys[(size_t)M_ROWS * H_DIM];  // keys int8 (per-row scaled)
__device__ int8_t g_W1T[(size_t)H_DIM * H_DIM];    // W1_bot^T [n][k] int8 (per-n scaled)
__device__ float g_sa[M_ROWS];                     // keys row scales
__device__ float g_sb[H_DIM];                      // W1T row scales
__device__ float g_sbinv[H_DIM];
__device__ float g_base[B_DIM * H_DIM];            // q @ W1_top + b1
__device__ float g_nullrow[H_DIM];
__device__ float g_newrow[H_DIM];
__device__ float g_partial[4 * M_ROWS];

// ---------------- helpers ----------------
__device__ __forceinline__ float gelu_exact(float x) {
    return 0.5f * x * (1.0f + erff(x * 0.70710678118654752f));
}
// tanh-form gelu; with --use_fast_math tanhf lowers to MUFU.TANH
__device__ __forceinline__ float gelu_fast(float x) {
    float x3 = x * x * x;
    return 0.5f * x * (1.0f + tanhf(0.7978845608028654f * fmaf(0.044715f, x3, x)));
}
__device__ __forceinline__ uint32_t smem_to_u32(const void* p) {
    uint32_t a;
    asm("{ .reg .u64 t; cvta.to.shared.u64 t, %1; cvt.u32.u64 %0, t; }" : "=r"(a) : "l"(p));
    return a;
}
__device__ __forceinline__ void cp16(uint32_t s, const void* g) {
    asm volatile("cp.async.cg.shared.global [%0], [%1], 16;" :: "r"(s), "l"(g));
}
__device__ __forceinline__ void ldsm4(uint32_t& r0, uint32_t& r1, uint32_t& r2,
                                      uint32_t& r3, uint32_t addr) {
    asm volatile("ldmatrix.sync.aligned.m8n8.x4.shared.b16 {%0,%1,%2,%3}, [%4];"
                 : "=r"(r0), "=r"(r1), "=r"(r2), "=r"(r3) : "r"(addr));
}
__device__ __forceinline__ void mma_i8(int* d, const uint32_t* a, uint32_t b0, uint32_t b1) {
    asm volatile(
        "mma.sync.aligned.m16n8k32.row.col.s32.s8.s8.s32 "
        "{%0,%1,%2,%3}, {%4,%5,%6,%7}, {%8,%9}, {%0,%1,%2,%3};"
        : "+r"(d[0]), "+r"(d[1]), "+r"(d[2]), "+r"(d[3])
        : "r"(a[0]), "r"(a[1]), "r"(a[2]), "r"(a[3]), "r"(b0), "r"(b1));
}
__device__ __forceinline__ int q8(float x, float inv) {
    return __float2int_rn(x * inv) & 255;
}

// smem layout (bytes); padded rows: 128B data + 16 pad = 144B; 3-stage pipeline
#define ROW_B 144
#define ABUF 18432                     // 128 rows * 144
#define BBUF 36864                     // 256 rows * 144
#define B_REG (3 * ABUF)               // 55296
#define PART_OFF (B_REG + 3 * BBUF)    // 165888
#define BASE_OFF (PART_OFF + 2048)     // 167936
#define W2S_OFF (BASE_OFF + 1024)      // 168960
#define SA_OFF (W2S_OFF + 1024)        // 169984
#define SB_OFF (SA_OFF + 512)          // 170496
#define SMEM_MAIN (SB_OFF + 1024)      // 171520

// ---------------- prep: keys fp32 -> int8 per-row ----------------
__global__ __launch_bounds__(256) void k_conv(const float* __restrict__ keys) {
    int wid = threadIdx.x >> 5, l = threadIdx.x & 31;
    int row = blockIdx.x * 8 + wid;
    const float4* src = reinterpret_cast<const float4*>(keys + (size_t)row * H_DIM);
    float4 v[8];
    float mx = 0.f;
#pragma unroll
    for (int i = 0; i < 8; ++i) {
        v[i] = src[l + i * 32];
        mx = fmaxf(mx, fmaxf(fmaxf(fabsf(v[i].x), fabsf(v[i].y)),
                             fmaxf(fabsf(v[i].z), fabsf(v[i].w))));
    }
#pragma unroll
    for (int s = 16; s > 0; s >>= 1) mx = fmaxf(mx, __shfl_xor_sync(0xffffffffu, mx, s));
    float inv = mx > 0.f ? 127.f / mx : 0.f;
    if (l == 0) g_sa[row] = mx * (1.f / 127.f);
    uint32_t* dst = reinterpret_cast<uint32_t*>(g_keys + (size_t)row * H_DIM);
#pragma unroll
    for (int i = 0; i < 8; ++i) {
        uint32_t p = q8(v[i].x, inv) | (q8(v[i].y, inv) << 8) |
                     (q8(v[i].z, inv) << 16) | (q8(v[i].w, inv) << 24);
        dst[l + i * 32] = p;
    }
}

// ---------------- prep: per-column max of W1_bot -> g_sb ----------------
__global__ __launch_bounds__(256) void k_sb(const float* __restrict__ W1) {
    __shared__ float r[256];
    int t = threadIdx.x;
    int nl = t & 15, slice = t >> 4;
    int n = blockIdx.x * 16 + nl;
    float mx = 0.f;
#pragma unroll 4
    for (int kk = 0; kk < 64; ++kk) {
        int k = slice * 64 + kk;
        mx = fmaxf(mx, fabsf(W1[(size_t)(H_DIM + k) * H_DIM + n]));
    }
    r[t] = mx;
    __syncthreads();
    if (t < 16) {
        float m = 0.f;
#pragma unroll
        for (int s = 0; s < 16; ++s) m = fmaxf(m, r[s * 16 + t]);
        g_sb[blockIdx.x * 16 + t] = m * (1.f / 127.f);
        g_sbinv[blockIdx.x * 16 + t] = m > 0.f ? 127.f / m : 0.f;
    }
}

// ---------------- prep: W1_bot^T -> int8 (transpose + quantize) ----------------
__global__ __launch_bounds__(256) void k_w1t(const float* __restrict__ W1) {
    __shared__ float tile[32][33];
    int tx = threadIdx.x, ty = threadIdx.y;
    int kb = blockIdx.x * 32, nb = blockIdx.y * 32;
#pragma unroll
    for (int i = 0; i < 4; ++i) {
        int kl = ty + i * 8;
        tile[kl][tx] = W1[(size_t)(H_DIM + kb + kl) * H_DIM + nb + tx];
    }
    __syncthreads();
#pragma unroll
    for (int i = 0; i < 4; ++i) {
        int nl = ty + i * 8;
        int n = nb + nl;
        float inv = g_sbinv[n];
        g_W1T[(size_t)n * H_DIM + kb + tx] = (int8_t)__float2int_rn(tile[tx][nl] * inv);
    }
}

// ---------------- prep: g_base = q @ W1_top + b1 (fp32) ----------------
__global__ __launch_bounds__(256) void k_base(
    const float* __restrict__ q, const float* __restrict__ W1, const float* __restrict__ b1) {
    __shared__ float qs[8 * H_DIM];
    int t = threadIdx.x;
    int b0 = blockIdx.y * 8, n0 = blockIdx.x * 64;
    const float4* qsrc = reinterpret_cast<const float4*>(q + (size_t)b0 * H_DIM);
    float4* qdst = reinterpret_cast<float4*>(qs);
#pragma unroll
    for (int i = 0; i < 8; ++i) qdst[t + i * 256] = qsrc[t + i * 256];
    __syncthreads();
    int tn = t & 63, tb = t >> 6;
    int n = n0 + tn;
    float a0 = 0.f, a1 = 0.f;
    const float* qa = qs + tb * H_DIM;
    const float* qb = qs + (tb + 4) * H_DIM;
#pragma unroll 8
    for (int k = 0; k < H_DIM; ++k) {
        float w = W1[(size_t)k * H_DIM + n];
        a0 = fmaf(qa[k], w, a0);
        a1 = fmaf(qb[k], w, a1);
    }
    float bias = b1[n];
    g_base[(size_t)(b0 + tb) * H_DIM + n] = a0 + bias;
    g_base[(size_t)(b0 + tb + 4) * H_DIM + n] = a1 + bias;
}

// ---------------- prep: null/new rows through W1_bot (fp32, parallel) ----------------
__global__ __launch_bounds__(256) void k_rows(
    const float* __restrict__ W1, const float* __restrict__ nulla, const float* __restrict__ newa) {
    __shared__ float ns[H_DIM], ws[H_DIM];
    __shared__ float rN[256], rW[256];
    int t = threadIdx.x;
#pragma unroll
    for (int i = 0; i < 4; ++i) {
        ns[t + i * 256] = nulla[t + i * 256];
        ws[t + i * 256] = newa[t + i * 256];
    }
    __syncthreads();
    int nl = t & 15;
    int slice = t >> 4;
    int n = blockIdx.x * 16 + nl;
    float an = 0.f, aw = 0.f;
#pragma unroll 4
    for (int kk = 0; kk < 64; ++kk) {
        int k = slice * 64 + kk;
        float w = W1[(size_t)(H_DIM + k) * H_DIM + n];
        an = fmaf(ns[k], w, an);
        aw = fmaf(ws[k], w, aw);
    }
    rN[t] = an; rW[t] = aw;
    __syncthreads();
    if (t < 16) {
        float a = 0.f, w = 0.f;
#pragma unroll
        for (int s = 0; s < 16; ++s) { a += rN[s * 16 + t]; w += rW[s * 16 + t]; }
        g_nullrow[blockIdx.x * 16 + t] = a;
        g_newrow[blockIdx.x * 16 + t] = w;
    }
}

// ---------------- null/new slot scores (exact fp32) ----------------
__global__ __launch_bounds__(256) void k_nullnew(
    const float* __restrict__ W2, const float* __restrict__ b2,
    const float* __restrict__ ms, float* __restrict__ out) {
    __shared__ float sN[256], sW[256];
    int b = blockIdx.x, t = threadIdx.x;
    float aN = 0.f, aW = 0.f;
    for (int n = t; n < H_DIM; n += 256) {
        float bb = g_base[(size_t)b * H_DIM + n];
        float w2 = W2[n];
        aN += gelu_exact(bb + g_nullrow[n]) * w2;
        aW += gelu_exact(bb + g_newrow[n]) * w2;
    }
    sN[t] = aN; sW[t] = aW;
    __syncthreads();
    for (int s = 128; s > 0; s >>= 1) {
        if (t < s) { sN[t] += sN[t + s]; sW[t] += sW[t + s]; }
        __syncthreads();
    }
    if (t == 0) {
        float bias = b2[0], m = ms[b];
        out[(size_t)b * S_DIM + 0]   = sN[0] + bias - m;
        out[(size_t)b * S_DIM + 513] = sW[0] + bias + m;
    }
}

// ---------------- main fused int8 GEMM + gelu + W2 reduce ----------------
// grid (4 n-quarters, 512 m-tiles), 256 threads = 8 warps (wm in {0,1}, wn in {0..3})
// warp tile 64m x 64n; K chunk 128 i8 (4 k32 mma steps); 3-stage cp.async pipeline
__global__ __launch_bounds__(256, 1) void ntm_main(const float* __restrict__ W2) {
    extern __shared__ char smem[];
    const uint32_t su = smem_to_u32(smem);
    const int tid = threadIdx.x;
    const int wid = tid >> 5;
    const int l = tid & 31;
    const int wm = wid & 1;
    const int wn = wid >> 1;
    const int nq = blockIdx.x;
    const int m_base = blockIdx.y * 128;
    const int b = blockIdx.y >> 2;

    float* part = reinterpret_cast<float*>(smem + PART_OFF);
    float* base_sh = reinterpret_cast<float*>(smem + BASE_OFF);
    float* w2_sh = reinterpret_cast<float*>(smem + W2S_OFF);
    float* sa_sh = reinterpret_cast<float*>(smem + SA_OFF);
    float* sb_sh = reinterpret_cast<float*>(smem + SB_OFF);

    base_sh[tid] = g_base[(size_t)b * H_DIM + nq * 256 + tid];
    w2_sh[tid] = W2[nq * 256 + tid];
    sb_sh[tid] = g_sb[nq * 256 + tid];
    if (tid < 128) sa_sh[tid] = g_sa[m_base + tid];

    const char* asrc = reinterpret_cast<const char*>(g_keys) + (size_t)m_base * H_DIM;
    const char* bsrc = reinterpret_cast<const char*>(g_W1T) + (size_t)nq * 256 * H_DIM;

    auto stage = [&](int c, int buf) {
        const char* ac = asrc + c * 128;  // 128 i8 = 128B per row chunk
        const char* bc = bsrc + c * 128;
        uint32_t sa = su + buf * ABUF;
        uint32_t sb = su + B_REG + buf * BBUF;
#pragma unroll
        for (int i = 0; i < 4; ++i) {
            int idx = tid + i * 256;
            int row = idx >> 3, u = idx & 7;
            cp16(sa + row * ROW_B + u * 16, ac + (size_t)row * H_DIM + u * 16);
        }
#pragma unroll
        for (int i = 0; i < 8; ++i) {
            int idx = tid + i * 256;
            int row = idx >> 3, u = idx & 7;
            cp16(sb + row * ROW_B + u * 16, bc + (size_t)row * H_DIM + u * 16);
        }
        asm volatile("cp.async.commit_group;" ::: "memory");
    };

    int acc[4][8][4];
#pragma unroll
    for (int i = 0; i < 4; ++i)
#pragma unroll
        for (int j = 0; j < 8; ++j)
#pragma unroll
            for (int r = 0; r < 4; ++r) acc[i][j][r] = 0;

    const int aRow = wm * 64 + (l & 7) + ((l >> 3) & 1) * 8;
    const uint32_t aKoff = (uint32_t)(l >> 4) * 16;
    const int bRow = wn * 64 + ((l >> 4) & 1) * 8 + (l & 7);
    const uint32_t bKoff = (uint32_t)((l >> 3) & 1) * 16;

    stage(0, 0);
    stage(1, 1);

#pragma unroll 1
    for (int c = 0; c < 8; ++c) {
        if (c < 7) {
            asm volatile("cp.async.wait_group 1;" ::: "memory");
        } else {
            asm volatile("cp.async.wait_group 0;" ::: "memory");
        }
        __syncthreads();
        if (c < 6) stage(c + 2, (c + 2) % 3);

        const int buf = c % 3;
        const uint32_t baseA = su + buf * ABUF;
        const uint32_t baseB = su + B_REG + buf * BBUF;

#pragma unroll
        for (int ks = 0; ks < 4; ++ks) {  // 4 x k32 covers 128B chunk
            uint32_t a[4][4];
#pragma unroll
            for (int mi = 0; mi < 4; ++mi) {
                uint32_t addr = baseA + (uint32_t)(aRow + mi * 16) * ROW_B + ks * 32 + aKoff;
                ldsm4(a[mi][0], a[mi][1], a[mi][2], a[mi][3], addr);
            }
            uint32_t bfr[4][4];
#pragma unroll
            for (int jp = 0; jp < 4; ++jp) {
                uint32_t addr = baseB + (uint32_t)(bRow + jp * 16) * ROW_B + ks * 32 + bKoff;
                ldsm4(bfr[jp][0], bfr[jp][1], bfr[jp][2], bfr[jp][3], addr);
            }
#pragma unroll
            for (int mi = 0; mi < 4; ++mi)
#pragma unroll
                for (int j = 0; j < 8; ++j)
                    mma_i8(acc[mi][j], a[mi], bfr[j >> 1][(j & 1) * 2], bfr[j >> 1][(j & 1) * 2 + 1]);
        }
    }

    // epilogue: x = base + sa*sb*acc ; score partial = sum gelu(x)*W2
    float s[4][2];
#pragma unroll
    for (int mi = 0; mi < 4; ++mi) { s[mi][0] = 0.f; s[mi][1] = 0.f; }
#pragma unroll
    for (int mi = 0; mi < 4; ++mi) {
        float sa0 = sa_sh[wm * 64 + mi * 16 + (l >> 2)];
        float sa1 = sa_sh[wm * 64 + mi * 16 + (l >> 2) + 8];
#pragma unroll
        for (int j = 0; j < 8; ++j) {
            int nb = wn * 64 + j * 8 + (l & 3) * 2;
            float sc0 = sb_sh[nb], sc1 = sb_sh[nb + 1];
            float w0 = w2_sh[nb], w1 = w2_sh[nb + 1];
            float bb0 = base_sh[nb], bb1 = base_sh[nb + 1];
            float x0 = fmaf((float)acc[mi][j][0], sa0 * sc0, bb0);
            float x1 = fmaf((float)acc[mi][j][1], sa0 * sc1, bb1);
            float x2 = fmaf((float)acc[mi][j][2], sa1 * sc0, bb0);
            float x3 = fmaf((float)acc[mi][j][3], sa1 * sc1, bb1);
            s[mi][0] += gelu_fast(x0) * w0 + gelu_fast(x1) * w1;
            s[mi][1] += gelu_fast(x2) * w0 + gelu_fast(x3) * w1;
        }
    }
#pragma unroll
    for (int mi = 0; mi < 4; ++mi) {
#pragma unroll
        for (int h = 0; h < 2; ++h) {
            float v = s[mi][h];
            v += __shfl_xor_sync(0xffffffffu, v, 1);
            v += __shfl_xor_sync(0xffffffffu, v, 2);
            if ((l & 3) == 0) {
                int row = wm * 64 + mi * 16 + (l >> 2) + h * 8;
                part[wn * 128 + row] = v;
            }
        }
    }
    __syncthreads();
    if (tid < 128) {
        float v = part[tid] + part[128 + tid] + part[256 + tid] + part[384 + tid];
        g_partial[(size_t)nq * M_ROWS + m_base + tid] = v;
    }
}

// ---------------- combine partials + bias + mention + mask ----------------
__global__ __launch_bounds__(512) void k_combine(
    const float* __restrict__ b2, const float* __restrict__ ms,
    const int* __restrict__ es, float* __restrict__ out) {
    int b = blockIdx.x, e = threadIdx.x;
    size_t m = (size_t)b * E_DIM + e;
    float v = g_partial[m] + g_partial[M_ROWS + m] + g_partial[2 * (size_t)M_ROWS + m] +
              g_partial[3 * (size_t)M_ROWS + m] + b2[0] + ms[b];
    if (e >= es[b]) v += NEG_V;
    out[(size_t)b * S_DIM + 1 + e] = v;
}

// ---------------- launch ----------------
extern "C" void kernel_launch(void* const* d_in, const int* in_sizes, int n_in,
                              void* d_out, int out_size) {
    const float* query = (const float*)d_in[0];
    const float* keys  = (const float*)d_in[1];
    const int*   esz   = (const int*)d_in[2];
    const float* msc   = (const float*)d_in[3];
    const float* W1    = (const float*)d_in[4];
    const float* b1    = (const float*)d_in[5];
    const float* W2    = (const float*)d_in[6];
    const float* b2    = (const float*)d_in[7];
    const float* nulla = (const float*)d_in[8];
    const float* newa  = (const float*)d_in[9];
    float* out = (float*)d_out;

    cudaFuncSetAttribute(ntm_main, cudaFuncAttributeMaxDynamicSharedMemorySize, SMEM_MAIN);

    k_conv<<<8192, 256>>>(keys);
    k_sb<<<64, 256>>>(W1);
    k_w1t<<<dim3(32, 32), dim3(32, 8)>>>(W1);
    k_base<<<dim3(16, 16), 256>>>(query, W1, b1);
    k_rows<<<64, 256>>>(W1, nulla, newa);
    k_nullnew<<<B_DIM, 256>>>(W2, b2, msc, out);
    ntm_main<<<dim3(4, 512), 256, SMEM_MAIN>>>(W2);
    k_combine<<<B_DIM, 512>>>(b2, msc, esz, out);
}

// round 6
// speedup vs baseline: 2.2890x; 2.2890x over previous
#include <cuda_runtime.h>
#include <cuda_bf16.h>
#include <cstdint>

#define B_DIM 128
#define E_DIM 512
#define H_DIM 1024
#define S_DIM 514
#define M_ROWS 65536
#define NEG_V (-1000000.0f)

// ---------------- device scratch ----------------
__device__ __nv_bfloat16 g_keys[(size_t)M_ROWS * H_DIM];  // keys in bf16
__device__ __nv_bfloat16 g_W1T[H_DIM * H_DIM];            // W1_bot^T [n][k] bf16
__device__ float g_basep[8 * B_DIM * H_DIM];              // k-split partials
__device__ float g_base[B_DIM * H_DIM];                   // q @ W1_top + b1
__device__ float g_nullrow[H_DIM];
__device__ float g_newrow[H_DIM];
__device__ float g_partial[4 * M_ROWS];

// ---------------- helpers ----------------
__device__ __forceinline__ uint32_t pack2(float a, float b) {
    __nv_bfloat162 h = __floats2bfloat162_rn(a, b);
    return reinterpret_cast<uint32_t&>(h);
}
__device__ __forceinline__ float gelu_exact(float x) {
    return 0.5f * x * (1.0f + erff(x * 0.70710678118654752f));
}
// tanh-form gelu via MUFU.TANH (flag-independent)
__device__ __forceinline__ float gelu_fast(float x) {
    float u = 0.7978845608028654f * fmaf(0.044715f * x, x * x, x);
    float t;
    asm("tanh.approx.f32 %0, %1;" : "=f"(t) : "f"(u));
    return 0.5f * x * (1.0f + t);
}
__device__ __forceinline__ uint32_t smem_to_u32(const void* p) {
    uint32_t a;
    asm("{ .reg .u64 t; cvta.to.shared.u64 t, %1; cvt.u32.u64 %0, t; }" : "=r"(a) : "l"(p));
    return a;
}
__device__ __forceinline__ void cp16(uint32_t s, const void* g) {
    asm volatile("cp.async.cg.shared.global [%0], [%1], 16;" :: "r"(s), "l"(g));
}
__device__ __forceinline__ void ldsm4(uint32_t& r0, uint32_t& r1, uint32_t& r2,
                                      uint32_t& r3, uint32_t addr) {
    asm volatile("ldmatrix.sync.aligned.m8n8.x4.shared.b16 {%0,%1,%2,%3}, [%4];"
                 : "=r"(r0), "=r"(r1), "=r"(r2), "=r"(r3) : "r"(addr));
}
__device__ __forceinline__ void mma16816(float* d, const uint32_t* a,
                                         uint32_t b0, uint32_t b1) {
    asm volatile(
        "mma.sync.aligned.m16n8k16.row.col.f32.bf16.bf16.f32 "
        "{%0,%1,%2,%3}, {%4,%5,%6,%7}, {%8,%9}, {%0,%1,%2,%3};"
        : "+f"(d[0]), "+f"(d[1]), "+f"(d[2]), "+f"(d[3])
        : "r"(a[0]), "r"(a[1]), "r"(a[2]), "r"(a[3]), "r"(b0), "r"(b1));
}

// smem layout (bytes); padded rows: 72 bf16 = 144B; 3-stage pipeline
#define ROW_B 144
#define ABUF 18432                 // 128 rows * 144
#define BBUF 36864                 // 256 rows * 144
#define B_REG (3 * ABUF)           // 55296
#define PART_OFF (B_REG + 3 * BBUF)        // 165888
#define BASE_OFF (PART_OFF + 2048)         // 167936
#define W2S_OFF (BASE_OFF + 1024)          // 168960
#define SMEM_MAIN (W2S_OFF + 1024)         // 169984

// ---------------- prep: keys fp32 -> bf16 ----------------
__global__ __launch_bounds__(256) void k_conv(const float* __restrict__ keys) {
    size_t stride = (size_t)gridDim.x * 256 * 4;
    for (size_t i = ((size_t)blockIdx.x * 256 + threadIdx.x) * 4;
         i < (size_t)M_ROWS * H_DIM; i += stride) {
        float4 f = *reinterpret_cast<const float4*>(keys + i);
        uint2 o;
        o.x = pack2(f.x, f.y);
        o.y = pack2(f.z, f.w);
        *reinterpret_cast<uint2*>(reinterpret_cast<char*>(g_keys) + i * 2) = o;
    }
}

// ---------------- prep: W1_bot^T -> bf16 ----------------
__global__ __launch_bounds__(256) void k_w1t(const float* __restrict__ W1) {
    __shared__ float tile[32][33];
    int tx = threadIdx.x, ty = threadIdx.y;
    int kb = blockIdx.x * 32, nb = blockIdx.y * 32;
#pragma unroll
    for (int i = 0; i < 4; ++i) {
        int kl = ty + i * 8;
        tile[kl][tx] = W1[(size_t)(H_DIM + kb + kl) * H_DIM + nb + tx];
    }
    __syncthreads();
#pragma unroll
    for (int i = 0; i < 4; ++i) {
        int nl = ty + i * 8;
        g_W1T[(size_t)(nb + nl) * H_DIM + kb + tx] = __float2bfloat16(tile[tx][nl]);
    }
}

// ---------------- prep: k-split partials of q @ W1_top ----------------
// grid (16 n-blocks, 16 b-blocks, 8 k-slices), 256 threads
__global__ __launch_bounds__(256) void k_base(
    const float* __restrict__ q, const float* __restrict__ W1) {
    __shared__ float qs[8 * 128];
    int t = threadIdx.x;
    int n0 = blockIdx.x * 64, b0 = blockIdx.y * 8, k0 = blockIdx.z * 128;
    {
        int r = t >> 5, c = t & 31;   // 8 rows x 32 threads x float4 = 1024 floats
        *reinterpret_cast<float4*>(qs + r * 128 + c * 4) =
            *reinterpret_cast<const float4*>(q + (size_t)(b0 + r) * H_DIM + k0 + c * 4);
    }
    __syncthreads();
    int tn = t & 63, tb = t >> 6;
    int n = n0 + tn;
    float a0 = 0.f, a1 = 0.f;
    const float* qa = qs + tb * 128;
    const float* qb = qs + (tb + 4) * 128;
#pragma unroll 8
    for (int kk = 0; kk < 128; ++kk) {
        float w = W1[(size_t)(k0 + kk) * H_DIM + n];
        a0 = fmaf(qa[kk], w, a0);
        a1 = fmaf(qb[kk], w, a1);
    }
    float* dst = g_basep + (size_t)blockIdx.z * B_DIM * H_DIM;
    dst[(size_t)(b0 + tb) * H_DIM + n] = a0;
    dst[(size_t)(b0 + tb + 4) * H_DIM + n] = a1;
}

// ---------------- prep: combine k-split partials + b1 -> g_base ----------------
__global__ __launch_bounds__(256) void k_basecomb(const float* __restrict__ b1) {
    int i = blockIdx.x * 256 + threadIdx.x;   // grid 512 -> 131072
    float v = b1[i & (H_DIM - 1)];
#pragma unroll
    for (int s = 0; s < 8; ++s) v += g_basep[(size_t)s * B_DIM * H_DIM + i];
    g_base[i] = v;
}

// ---------------- prep: null/new rows through W1_bot (parallel, grid=64) ----------------
__global__ __launch_bounds__(256) void k_rows(
    const float* __restrict__ W1, const float* __restrict__ nulla, const float* __restrict__ newa) {
    __shared__ float ns[H_DIM], ws[H_DIM];
    __shared__ float rN[256], rW[256];
    int t = threadIdx.x;
#pragma unroll
    for (int i = 0; i < 4; ++i) {
        ns[t + i * 256] = nulla[t + i * 256];
        ws[t + i * 256] = newa[t + i * 256];
    }
    __syncthreads();
    int nl = t & 15;
    int slice = t >> 4;
    int n = blockIdx.x * 16 + nl;
    float an = 0.f, aw = 0.f;
#pragma unroll 4
    for (int kk = 0; kk < 64; ++kk) {
        int k = slice * 64 + kk;
        float w = W1[(size_t)(H_DIM + k) * H_DIM + n];
        an = fmaf(ns[k], w, an);
        aw = fmaf(ws[k], w, aw);
    }
    rN[t] = an; rW[t] = aw;
    __syncthreads();
    if (t < 16) {
        float a = 0.f, w = 0.f;
#pragma unroll
        for (int s = 0; s < 16; ++s) { a += rN[s * 16 + t]; w += rW[s * 16 + t]; }
        g_nullrow[blockIdx.x * 16 + t] = a;
        g_newrow[blockIdx.x * 16 + t] = w;
    }
}

// ---------------- null/new slot scores (exact fp32) ----------------
__global__ __launch_bounds__(256) void k_nullnew(
    const float* __restrict__ W2, const float* __restrict__ b2,
    const float* __restrict__ ms, float* __restrict__ out) {
    __shared__ float sN[256], sW[256];
    int b = blockIdx.x, t = threadIdx.x;
    float aN = 0.f, aW = 0.f;
    for (int n = t; n < H_DIM; n += 256) {
        float bb = g_base[(size_t)b * H_DIM + n];
        float w2 = W2[n];
        aN += gelu_exact(bb + g_nullrow[n]) * w2;
        aW += gelu_exact(bb + g_newrow[n]) * w2;
    }
    sN[t] = aN; sW[t] = aW;
    __syncthreads();
    for (int s = 128; s > 0; s >>= 1) {
        if (t < s) { sN[t] += sN[t + s]; sW[t] += sW[t + s]; }
        __syncthreads();
    }
    if (t == 0) {
        float bias = b2[0], m = ms[b];
        out[(size_t)b * S_DIM + 0]   = sN[0] + bias - m;
        out[(size_t)b * S_DIM + 513] = sW[0] + bias + m;
    }
}

// ---------------- main fused GEMM + gelu + W2 reduce ----------------
// grid (4 n-quarters, 512 m-tiles), 256 threads = 8 warps (wm in {0,1}, wn in {0..3})
// warp tile 64m x 64n; K chunk 64; 3-stage cp.async pipeline, 1 sync/chunk
__global__ __launch_bounds__(256, 1) void ntm_main(const float* __restrict__ W2) {
    extern __shared__ char smem[];
    const uint32_t su = smem_to_u32(smem);
    const int tid = threadIdx.x;
    const int wid = tid >> 5;
    const int l = tid & 31;
    const int wm = wid & 1;
    const int wn = wid >> 1;
    const int nq = blockIdx.x;
    const int m_base = blockIdx.y * 128;
    const int b = blockIdx.y >> 2;

    float* part = reinterpret_cast<float*>(smem + PART_OFF);
    float* base_sh = reinterpret_cast<float*>(smem + BASE_OFF);
    float* w2_sh = reinterpret_cast<float*>(smem + W2S_OFF);

    base_sh[tid] = g_base[(size_t)b * H_DIM + nq * 256 + tid];
    w2_sh[tid] = W2[nq * 256 + tid];

    const char* asrc = reinterpret_cast<const char*>(g_keys) + (size_t)m_base * H_DIM * 2;
    const char* bsrc = reinterpret_cast<const char*>(g_W1T) + (size_t)nq * 256 * H_DIM * 2;

    auto stage = [&](int c, int buf) {
        const char* ac = asrc + c * 128;  // 64 bf16 = 128B per row chunk
        const char* bc = bsrc + c * 128;
        uint32_t sa = su + buf * ABUF;
        uint32_t sb = su + B_REG + buf * BBUF;
#pragma unroll
        for (int i = 0; i < 4; ++i) {
            int idx = tid + i * 256;
            int row = idx >> 3, u = idx & 7;
            cp16(sa + row * ROW_B + u * 16, ac + (size_t)row * 2048 + u * 16);
        }
#pragma unroll
        for (int i = 0; i < 8; ++i) {
            int idx = tid + i * 256;
            int row = idx >> 3, u = idx & 7;
            cp16(sb + row * ROW_B + u * 16, bc + (size_t)row * 2048 + u * 16);
        }
        asm volatile("cp.async.commit_group;" ::: "memory");
    };

    float acc[4][8][4];
#pragma unroll
    for (int i = 0; i < 4; ++i)
#pragma unroll
        for (int j = 0; j < 8; ++j)
#pragma unroll
            for (int r = 0; r < 4; ++r) acc[i][j][r] = 0.f;

    const int aRow = wm * 64 + (l & 7) + ((l >> 3) & 1) * 8;
    const uint32_t aKoff = (uint32_t)(l >> 4) * 16;
    const int bRow = wn * 64 + ((l >> 4) & 1) * 8 + (l & 7);
    const uint32_t bKoff = (uint32_t)((l >> 3) & 1) * 16;

    stage(0, 0);
    stage(1, 1);

#pragma unroll 1
    for (int c = 0; c < 16; ++c) {
        if (c < 15) {
            asm volatile("cp.async.wait_group 1;" ::: "memory");
        } else {
            asm volatile("cp.async.wait_group 0;" ::: "memory");
        }
        __syncthreads();
        if (c < 14) stage(c + 2, (c + 2) % 3);

        const int buf = c % 3;
        const uint32_t baseA = su + buf * ABUF;
        const uint32_t baseB = su + B_REG + buf * BBUF;

#pragma unroll
        for (int ks = 0; ks < 4; ++ks) {
            uint32_t a[4][4];
#pragma unroll
            for (int mi = 0; mi < 4; ++mi) {
                uint32_t addr = baseA + (uint32_t)(aRow + mi * 16) * ROW_B + ks * 32 + aKoff;
                ldsm4(a[mi][0], a[mi][1], a[mi][2], a[mi][3], addr);
            }
            uint32_t bfr[4][4];
#pragma unroll
            for (int jp = 0; jp < 4; ++jp) {
                uint32_t addr = baseB + (uint32_t)(bRow + jp * 16) * ROW_B + ks * 32 + bKoff;
                ldsm4(bfr[jp][0], bfr[jp][1], bfr[jp][2], bfr[jp][3], addr);
            }
#pragma unroll
            for (int mi = 0; mi < 4; ++mi)
#pragma unroll
                for (int j = 0; j < 8; ++j)
                    mma16816(acc[mi][j], a[mi], bfr[j >> 1][(j & 1) * 2], bfr[j >> 1][(j & 1) * 2 + 1]);
        }
    }

    // epilogue: gelu + W2 dot, reduce over this warp's 64 n-cols
    float s[4][2];
#pragma unroll
    for (int mi = 0; mi < 4; ++mi) { s[mi][0] = 0.f; s[mi][1] = 0.f; }
#pragma unroll
    for (int mi = 0; mi < 4; ++mi) {
#pragma unroll
        for (int j = 0; j < 8; ++j) {
            int nb = wn * 64 + j * 8 + (l & 3) * 2;
            float w0 = w2_sh[nb], w1 = w2_sh[nb + 1];
            float bb0 = base_sh[nb], bb1 = base_sh[nb + 1];
            s[mi][0] += gelu_fast(acc[mi][j][0] + bb0) * w0 + gelu_fast(acc[mi][j][1] + bb1) * w1;
            s[mi][1] += gelu_fast(acc[mi][j][2] + bb0) * w0 + gelu_fast(acc[mi][j][3] + bb1) * w1;
        }
    }
    __syncthreads();
#pragma unroll
    for (int mi = 0; mi < 4; ++mi) {
#pragma unroll
        for (int h = 0; h < 2; ++h) {
            float v = s[mi][h];
            v += __shfl_xor_sync(0xffffffffu, v, 1);
            v += __shfl_xor_sync(0xffffffffu, v, 2);
            if ((l & 3) == 0) {
                int row = wm * 64 + mi * 16 + (l >> 2) + h * 8;
                part[wn * 128 + row] = v;
            }
        }
    }
    __syncthreads();
    if (tid < 128) {
        float v = part[tid] + part[128 + tid] + part[256 + tid] + part[384 + tid];
        g_partial[(size_t)nq * M_ROWS + m_base + tid] = v;
    }
}

// ---------------- combine partials + bias + mention + mask ----------------
__global__ __launch_bounds__(512) void k_combine(
    const float* __restrict__ b2, const float* __restrict__ ms,
    const int* __restrict__ es, float* __restrict__ out) {
    int b = blockIdx.x, e = threadIdx.x;
    size_t m = (size_t)b * E_DIM + e;
    float v = g_partial[m] + g_partial[M_ROWS + m] + g_partial[2 * (size_t)M_ROWS + m] +
              g_partial[3 * (size_t)M_ROWS + m] + b2[0] + ms[b];
    if (e >= es[b]) v += NEG_V;
    out[(size_t)b * S_DIM + 1 + e] = v;
}

// ---------------- launch ----------------
extern "C" void kernel_launch(void* const* d_in, const int* in_sizes, int n_in,
                              void* d_out, int out_size) {
    const float* query = (const float*)d_in[0];
    const float* keys  = (const float*)d_in[1];
    const int*   esz   = (const int*)d_in[2];
    const float* msc   = (const float*)d_in[3];
    const float* W1    = (const float*)d_in[4];
    const float* b1    = (const float*)d_in[5];
    const float* W2    = (const float*)d_in[6];
    const float* b2    = (const float*)d_in[7];
    const float* nulla = (const float*)d_in[8];
    const float* newa  = (const float*)d_in[9];
    float* out = (float*)d_out;

    cudaFuncSetAttribute(ntm_main, cudaFuncAttributeMaxDynamicSharedMemorySize, SMEM_MAIN);

    k_conv<<<8192, 256>>>(keys);
    k_w1t<<<dim3(32, 32), dim3(32, 8)>>>(W1);
    k_base<<<dim3(16, 16, 8), 256>>>(query, W1);
    k_basecomb<<<512, 256>>>(b1);
    k_rows<<<64, 256>>>(W1, nulla, newa);
    k_nullnew<<<B_DIM, 256>>>(W2, b2, msc, out);
    ntm_main<<<dim3(4, 512), 256, SMEM_MAIN>>>(W2);
    k_combine<<<B_DIM, 512>>>(b2, msc, esz, out);
}